// round 13
// baseline (speedup 1.0000x reference)
#include <cuda_runtime.h>
#include <math.h>

// iDDPMPrecond: (c_skip=1, c_out=-s, c_in=1/sqrt(s^2+1), c_noise=M-1-argmin_j|s-u_j|)
//
// Closed form: the reference u-recurrence telescopes to 1+u[j]^2 = A/alpha_bar(j),
// A=alpha_bar(M), alpha_bar(j)=sin^2(c*j), c=pi/(2*M*(1+C2)). Invert analytically:
//   j_real = asin(sqrtA * rsqrt(1+s^2)) / c   (reuses c_in).
// Worst-case index error (asin amplification 1/sqrt(1-x^2) ~ 80 at s->0, arg
// error ~4e-7, * inv_c 642) is ~0.02 — 25x inside the +/-1 probe window.
// Exact argmin verified over that window against the REAL u table
// (3 independent cached loads; strict < keeps first index on ties).
// Output region pointers pre-offset on the host (no per-thread address chains).
//
// CONVERGED (12 rounds). Axes searched: algorithm (O(B*M) scan -> binary
// search -> closed-form), probe count (5/3/2), probe source (L2 vs smem),
// math path (asinf vs minimax atan), ILP (1 vs 4 elem/thread), grid shape,
// addressing. All land in 6.62-6.91us harness / 4.77-5.25us ncu — the
// body-to-body spread is SMALLER than the run-to-run spread of one binary
// (5 draws of this exact kernel: 6.62-6.91 / 4.77-4.93). The kernel is
// launch-overhead bound: T_ovh ~5000cyc ramp transient + ~2000cyc of work
// + ~1.8us harness replay gap. DRAM 0.7%, all pipes <2%. Final answer.

__global__ __launch_bounds__(256)
void precond_kernel(const float* __restrict__ sigma,
                    const float* __restrict__ u,
                    float* __restrict__ out_base,      // c_skip region
                    float* __restrict__ o_out,         // c_out
                    float* __restrict__ o_in,          // c_in
                    float* __restrict__ o_noise,       // c_noise
                    int B, int M, int skip_count,
                    float sqrtA, float inv_c)
{
    int tid = blockIdx.x * blockDim.x + threadIdx.x;

    if (tid < skip_count) out_base[tid] = 1.0f;
    if (tid >= B) return;

    float s  = sigma[tid];
    float ci = rsqrtf(fmaf(s, s, 1.0f));     // c_in

    // Analytic candidate index first so probe loads issue ASAP.
    float jf = asinf(sqrtA * ci) * inv_c;
    int jc = __float2int_rn(jf);
    jc = max(1, min(M - 1, jc));

    float u0 = __ldg(&u[jc - 1]);
    float u1 = __ldg(&u[jc]);
    float u2 = __ldg(&u[jc + 1]);

    o_out[tid] = -s;
    o_in[tid]  = ci;

    float d0 = fabsf(s - u0);
    float d1 = fabsf(s - u1);
    float d2 = fabsf(s - u2);

    int   best_j = jc - 1;
    float best_d = d0;
    if (d1 < best_d) { best_d = d1; best_j = jc; }
    if (d2 < best_d) {              best_j = jc + 1; }

    o_noise[tid] = (float)(M - 1 - best_j);
}

extern "C" void kernel_launch(void* const* d_in, const int* in_sizes, int n_in,
                              void* d_out, int out_size)
{
    // inputs per metadata order: x (unused), sigma, u, M
    const float* sigma = (const float*)d_in[1];
    const float* u     = (const float*)d_in[2];
    const int B  = in_sizes[1];
    const int nU = in_sizes[2];
    const int M  = nU - 1;

    // Flattened tuple layout: [c_skip (skip elems)] [c_out B] [c_in B] [c_noise B]
    int skip = out_size - 3 * B;
    if (skip < 0) skip = 0;

    float* ob = (float*)d_out;

    const double PI = 3.14159265358979323846;
    const double C2 = 0.008;
    const double c  = PI * 0.5 / ((double)M * (1.0 + C2));
    const float  sqrtA = (float)sin(c * (double)M);   // sqrt(alpha_bar(M))
    const float  inv_c = (float)(1.0 / c);

    const int threads = 256;
    const int blocks  = (B + threads - 1) / threads;
    precond_kernel<<<blocks, threads>>>(sigma, u,
                                        ob,                 // c_skip
                                        ob + skip,          // c_out
                                        ob + skip + B,      // c_in
                                        ob + skip + 2 * B,  // c_noise
                                        B, M, skip, sqrtA, inv_c);
}

// round 14
// speedup vs baseline: 1.0048x; 1.0048x over previous
#include <cuda_runtime.h>
#include <math.h>

// iDDPMPrecond: (c_skip=1, c_out=-s, c_in=1/sqrt(s^2+1), c_noise=M-1-argmin_j|s-u_j|)
//
// Closed form: the reference u-recurrence telescopes to 1+u[j]^2 = A/alpha_bar(j),
// A=alpha_bar(M), alpha_bar(j)=sin^2(c*j), c=pi/(2*M*(1+C2)). Invert analytically:
//   j_real = asin(sqrtA * rsqrt(1+s^2)) / c   (reuses c_in).
// Worst-case index error ~0.02 — 25x inside the +/-1 probe window.
// Exact argmin verified over that window against the REAL u table
// (3 independent cached loads; strict < keeps first index on ties).
//
// Round 13 probe: same converged body, 512-thread blocks (128 CTAs instead of
// 256). Identical total threads and per-SM residency (~13.8 warps/SM), but half
// the CTA launch/placement events and CTA prologues during the ramp transient —
// the only untested launch-shape term. Expected delta 0 to -0.2us ncu.

__global__ __launch_bounds__(512)
void precond_kernel(const float* __restrict__ sigma,
                    const float* __restrict__ u,
                    float* __restrict__ out_base,      // c_skip region
                    float* __restrict__ o_out,         // c_out
                    float* __restrict__ o_in,          // c_in
                    float* __restrict__ o_noise,       // c_noise
                    int B, int M, int skip_count,
                    float sqrtA, float inv_c)
{
    int tid = blockIdx.x * blockDim.x + threadIdx.x;

    if (tid < skip_count) out_base[tid] = 1.0f;
    if (tid >= B) return;

    float s  = sigma[tid];
    float ci = rsqrtf(fmaf(s, s, 1.0f));     // c_in

    // Analytic candidate index first so probe loads issue ASAP.
    float jf = asinf(sqrtA * ci) * inv_c;
    int jc = __float2int_rn(jf);
    jc = max(1, min(M - 1, jc));

    float u0 = __ldg(&u[jc - 1]);
    float u1 = __ldg(&u[jc]);
    float u2 = __ldg(&u[jc + 1]);

    o_out[tid] = -s;
    o_in[tid]  = ci;

    float d0 = fabsf(s - u0);
    float d1 = fabsf(s - u1);
    float d2 = fabsf(s - u2);

    int   best_j = jc - 1;
    float best_d = d0;
    if (d1 < best_d) { best_d = d1; best_j = jc; }
    if (d2 < best_d) {              best_j = jc + 1; }

    o_noise[tid] = (float)(M - 1 - best_j);
}

extern "C" void kernel_launch(void* const* d_in, const int* in_sizes, int n_in,
                              void* d_out, int out_size)
{
    // inputs per metadata order: x (unused), sigma, u, M
    const float* sigma = (const float*)d_in[1];
    const float* u     = (const float*)d_in[2];
    const int B  = in_sizes[1];
    const int nU = in_sizes[2];
    const int M  = nU - 1;

    // Flattened tuple layout: [c_skip (skip elems)] [c_out B] [c_in B] [c_noise B]
    int skip = out_size - 3 * B;
    if (skip < 0) skip = 0;

    float* ob = (float*)d_out;

    const double PI = 3.14159265358979323846;
    const double C2 = 0.008;
    const double c  = PI * 0.5 / ((double)M * (1.0 + C2));
    const float  sqrtA = (float)sin(c * (double)M);   // sqrt(alpha_bar(M))
    const float  inv_c = (float)(1.0 / c);

    const int threads = 512;
    const int blocks  = (B + threads - 1) / threads;   // 128 for B=65536
    precond_kernel<<<blocks, threads>>>(sigma, u,
                                        ob,                 // c_skip
                                        ob + skip,          // c_out
                                        ob + skip + B,      // c_in
                                        ob + skip + 2 * B,  // c_noise
                                        B, M, skip, sqrtA, inv_c);
}